// round 1
// baseline (speedup 1.0000x reference)
#include <cuda_runtime.h>
#include <cstdint>
#include <cstddef>

// Problem constants
#define Bc 256
#define Dc 256
#define Kc 1024
#define Ec 16

// Output offsets (floats) within d_out, in reference return order:
// cw_embed (B, D*E), one_hot (B, D, K), new_codebook (D, K, E), new_ema (D, K)
static const size_t OFF_EMB = 0;
static const size_t OFF_OH  = (size_t)Bc * Dc * Ec;                    // 1,048,576
static const size_t OFF_NCB = OFF_OH + (size_t)Bc * Dc * Kc;           // 68,157,440
static const size_t OFF_NEC = OFF_NCB + (size_t)Dc * Kc * Ec;          // 72,351,744

// ---- packed f32x2 helpers (Blackwell) ----
__device__ __forceinline__ unsigned long long pk2(float a, float b) {
    unsigned long long r;
    asm("mov.b64 %0,{%1,%2};" : "=l"(r) : "f"(a), "f"(b));
    return r;
}
__device__ __forceinline__ void upk2(unsigned long long v, float& a, float& b) {
    asm("mov.b64 {%0,%1},%2;" : "=f"(a), "=f"(b) : "l"(v));
}
__device__ __forceinline__ unsigned long long f2fma(unsigned long long a, unsigned long long b, unsigned long long c) {
    unsigned long long d;
    asm("fma.rn.f32x2 %0,%1,%2,%3;" : "=l"(d) : "l"(a), "l"(b), "l"(c));
    return d;
}
__device__ __forceinline__ unsigned long long f2add(unsigned long long a, unsigned long long b) {
    unsigned long long d;
    asm("add.rn.f32x2 %0,%1,%2;" : "=l"(d) : "l"(a), "l"(b));
    return d;
}
__device__ __forceinline__ unsigned long long f2mul(unsigned long long a, unsigned long long b) {
    unsigned long long d;
    asm("mul.rn.f32x2 %0,%1,%2;" : "=l"(d) : "l"(a), "l"(b));
    return d;
}

// Dynamic shared memory layout:
//   [0, 65536)            cpack : codebook[d] in k-pair interleaved layout
//                         cpack[(k>>1)*32 + e*2 + (k&1)] = codebook[d][k][e]
//   [65536, 69632)        c2    : per-k squared norms (1024 floats; pairs are
//                                 naturally adjacent for packed reads)
//   [69632, 70656)        sidx  : per-batch argmin index (256 ints)
//   [70656, 74752)        scnt  : per-k histogram (1024 ints)
#define SMEM_BYTES 74752

extern __shared__ unsigned char smem_raw[];

__global__ void __launch_bounds__(256, 2)
vq_kernel(const float* __restrict__ cw_q,
          const float* __restrict__ codebook,
          const float* __restrict__ ema,
          float* __restrict__ out)
{
    float* cpack = (float*)smem_raw;                                  // 16384 floats
    float* c2f   = (float*)(smem_raw + 65536);                        // 1024 floats
    unsigned long long* c2p = (unsigned long long*)(smem_raw + 65536);// 512 packed pairs
    int* sidx = (int*)(smem_raw + 65536 + 4096);                      // 256
    int* scnt = (int*)(smem_raw + 65536 + 4096 + 1024);               // 1024

    const int d = blockIdx.x;
    const int t = threadIdx.x;
    const float* cb_d = codebook + (size_t)d * (Kc * Ec);

    // ---- phase 1: stage codebook into pair-interleaved smem, zero histogram
    for (int i = t; i < Kc * Ec; i += 256) {
        float v = cb_d[i];
        int k = i >> 4, e = i & 15;
        cpack[(k >> 1) * 32 + e * 2 + (k & 1)] = v;
    }
    for (int i = t; i < Kc; i += 256) scnt[i] = 0;
    __syncthreads();

    // per-k squared norms
    for (int k = t; k < Kc; k += 256) {
        const float* cp = cpack + (k >> 1) * 32 + (k & 1);
        float s = 0.f;
        #pragma unroll
        for (int e = 0; e < 16; e++) { float c = cp[e * 2]; s += c * c; }
        c2f[k] = s;
    }
    __syncthreads();

    // ---- phase 2: argmin over K for batch b = t
    const int b = t;
    const float* xp = cw_q + (size_t)b * (Dc * Ec) + (size_t)d * Ec;
    float xf[16];
    {
        float4 v0 = ((const float4*)xp)[0];
        float4 v1 = ((const float4*)xp)[1];
        float4 v2 = ((const float4*)xp)[2];
        float4 v3 = ((const float4*)xp)[3];
        xf[0]=v0.x; xf[1]=v0.y; xf[2]=v0.z; xf[3]=v0.w;
        xf[4]=v1.x; xf[5]=v1.y; xf[6]=v1.z; xf[7]=v1.w;
        xf[8]=v2.x; xf[9]=v2.y; xf[10]=v2.z; xf[11]=v2.w;
        xf[12]=v3.x; xf[13]=v3.y; xf[14]=v3.z; xf[15]=v3.w;
    }
    float x2 = 0.f;
    unsigned long long xx[16];
    #pragma unroll
    for (int e = 0; e < 16; e++) { x2 += xf[e] * xf[e]; xx[e] = pk2(xf[e], xf[e]); }

    const unsigned long long X2 = pk2(x2, x2);
    const unsigned long long NT = pk2(-2.0f, -2.0f);
    const unsigned long long ZZ = pk2(0.0f, 0.0f);

    float best = 3.4e38f;
    int bidx = 0;

    const ulonglong2* cp2 = (const ulonglong2*)cpack;  // 8 ulonglong2 per k-pair row
    #pragma unroll 4
    for (int p = 0; p < Kc / 2; p++) {
        const ulonglong2* row = cp2 + p * 8;
        unsigned long long a0 = ZZ, a1 = ZZ;
        #pragma unroll
        for (int j = 0; j < 8; j++) {
            ulonglong2 v = row[j];
            a0 = f2fma(xx[2 * j],     v.x, a0);
            a1 = f2fma(xx[2 * j + 1], v.y, a1);
        }
        unsigned long long dot2  = f2add(a0, a1);
        unsigned long long s2    = f2add(X2, c2p[p]);          // x2 + c2   (matches ref order)
        unsigned long long dist2 = f2add(s2, f2mul(NT, dot2)); // (x2+c2) + (-2*xc)
        float d0, d1;
        upk2(dist2, d0, d1);
        float cd = d0; int ck = 2 * p;
        if (d1 < d0) { cd = d1; ck = 2 * p + 1; }   // strict: first-min semantics
        if (cd < best) { best = cd; bidx = ck; }
    }

    sidx[b] = bidx;
    atomicAdd(&scnt[bidx], 1);

    // cw_embed[b, d*16..] = codebook[d, bidx]  (read from smem BEFORE acc overwrite)
    {
        const float* ce = cpack + (bidx >> 1) * 32 + (bidx & 1);
        float* dst = out + OFF_EMB + (size_t)b * (Dc * Ec) + (size_t)d * Ec;
        #pragma unroll
        for (int q = 0; q < 4; q++) {
            float4 o = make_float4(ce[(4 * q + 0) * 2], ce[(4 * q + 1) * 2],
                                   ce[(4 * q + 2) * 2], ce[(4 * q + 3) * 2]);
            ((float4*)dst)[q] = o;
        }
    }
    __syncthreads();   // sidx/scnt complete; cpack reads complete

    // ---- phase 3: new_ema_counts, and zero the accumulator (reuse cpack region)
    for (int k = t; k < Kc; k += 256) {
        out[OFF_NEC + (size_t)d * Kc + k] =
            0.999f * ema[(size_t)d * Kc + k] + 0.001f * (float)scnt[k];
    }
    float* acc = cpack;  // reuse as update accumulator, plain [k][e] layout
    for (int i = t; i < Kc * Ec; i += 256) acc[i] = 0.f;
    __syncthreads();

    // ---- phase 4: scatter x into update accumulator
    #pragma unroll
    for (int e = 0; e < 16; e++) atomicAdd(&acc[bidx * Ec + e], xf[e]);
    __syncthreads();

    // ---- phase 5: EMA codebook update (re-read codebook coalesced from gmem)
    for (int i = t; i < Kc * Ec; i += 256) {
        int k = i >> 4;
        float cb = cb_d[i];
        float denom = ema[(size_t)d * Kc + k] + 1e-6f;
        float nc = 0.999f * cb + 0.001f * (acc[i] / denom);
        out[OFF_NCB + (size_t)d * (Kc * Ec) + i] = nc;
    }

    // ---- phase 6: one_hot slab for this d: out_oh[b, d, k] = (k == sidx[b])
    const size_t oh_d = OFF_OH + (size_t)d * Kc;
    for (int i = t; i < Bc * (Kc / 4); i += 256) {
        int bb = i >> 8;        // batch row (256 float4 chunks per row)
        int c4 = i & 255;       // float4 chunk index within the K dimension
        int idx = sidx[bb];
        int base = c4 * 4;
        float4 v;
        v.x = (idx == base + 0) ? 1.0f : 0.0f;
        v.y = (idx == base + 1) ? 1.0f : 0.0f;
        v.z = (idx == base + 2) ? 1.0f : 0.0f;
        v.w = (idx == base + 3) ? 1.0f : 0.0f;
        ((float4*)(out + oh_d + (size_t)bb * (Dc * Kc)))[c4] = v;
    }
}

extern "C" void kernel_launch(void* const* d_in, const int* in_sizes, int n_in,
                              void* d_out, int out_size)
{
    const float* cw_q     = (const float*)d_in[0];
    const float* codebook = (const float*)d_in[1];
    const float* ema      = (const float*)d_in[2];
    float* out            = (float*)d_out;

    cudaFuncSetAttribute(vq_kernel, cudaFuncAttributeMaxDynamicSharedMemorySize, SMEM_BYTES);
    vq_kernel<<<Dc, 256, SMEM_BYTES>>>(cw_q, codebook, ema, out);
}

// round 2
// speedup vs baseline: 1.1392x; 1.1392x over previous
#include <cuda_runtime.h>
#include <cstdint>
#include <cstddef>

// Problem constants
#define Bc 256
#define Dc 256
#define Kc 1024
#define Ec 16
#define KSPLIT 4
#define KH (Kc / KSPLIT)   // 256 codes per argmin block

// Output offsets (floats) within d_out, in reference return order:
// cw_embed (B, D*E), one_hot (B, D, K), new_codebook (D, K, E), new_ema (D, K)
static const size_t OFF_EMB = 0;
static const size_t OFF_OH  = (size_t)Bc * Dc * Ec;                    // 1,048,576
static const size_t OFF_NCB = OFF_OH + (size_t)Bc * Dc * Kc;           // 68,157,440
static const size_t OFF_NEC = OFF_NCB + (size_t)Dc * Kc * Ec;          // 72,351,744

// Scratch: per-(split, d, b) packed argmin key. Written non-atomically by the
// owning block, so no init pass is needed.
__device__ unsigned long long g_key[KSPLIT * Dc * Bc];

// ---- packed f32x2 helpers (Blackwell) ----
__device__ __forceinline__ unsigned long long pk2(float a, float b) {
    unsigned long long r;
    asm("mov.b64 %0,{%1,%2};" : "=l"(r) : "f"(a), "f"(b));
    return r;
}
__device__ __forceinline__ void upk2(unsigned long long v, float& a, float& b) {
    asm("mov.b64 {%0,%1},%2;" : "=f"(a), "=f"(b) : "l"(v));
}
__device__ __forceinline__ unsigned long long f2fma(unsigned long long a, unsigned long long b, unsigned long long c) {
    unsigned long long d;
    asm("fma.rn.f32x2 %0,%1,%2,%3;" : "=l"(d) : "l"(a), "l"(b), "l"(c));
    return d;
}
__device__ __forceinline__ unsigned long long f2add(unsigned long long a, unsigned long long b) {
    unsigned long long d;
    asm("add.rn.f32x2 %0,%1,%2;" : "=l"(d) : "l"(a), "l"(b));
    return d;
}
__device__ __forceinline__ unsigned long long f2mul(unsigned long long a, unsigned long long b) {
    unsigned long long d;
    asm("mul.rn.f32x2 %0,%1,%2;" : "=l"(d) : "l"(a), "l"(b));
    return d;
}

// Map float to an order-preserving uint (no NaNs expected).
__device__ __forceinline__ unsigned int orderable(float f) {
    unsigned int u = __float_as_uint(f);
    return (u & 0x80000000u) ? ~u : (u | 0x80000000u);
}

// =====================================================================
// Kernel A: argmin over one K-chunk. grid = (Dc, KSPLIT), block = 256.
// Static smem: 16 KB packed codebook chunk + 1 KB c2  -> 3 CTAs/SM.
// =====================================================================
__global__ void __launch_bounds__(256, 3)
vq_argmin(const float* __restrict__ cw_q,
          const float* __restrict__ codebook)
{
    // cpack[(k>>1)*32 + e*2 + (k&1)] = codebook[d][sp*KH + k][e]
    __shared__ float cpack[KH * Ec];         // 16 KB
    __shared__ float c2f[KH];                // 1 KB (pairs adjacent)

    const int d  = blockIdx.x;
    const int sp = blockIdx.y;
    const int t  = threadIdx.x;
    const float* cb = codebook + ((size_t)d * Kc + (size_t)sp * KH) * Ec;

    // stage + pack the codebook chunk
    #pragma unroll
    for (int i = t; i < KH * Ec; i += 256) {
        float v = cb[i];
        int k = i >> 4, e = i & 15;
        cpack[(k >> 1) * 32 + e * 2 + (k & 1)] = v;
    }
    __syncthreads();

    // per-k squared norms (KH == blockDim.x: one k per thread)
    {
        const int k = t;
        const float* cp = cpack + (k >> 1) * 32 + (k & 1);
        float s = 0.f;
        #pragma unroll
        for (int e = 0; e < 16; e++) { float c = cp[e * 2]; s += c * c; }
        c2f[k] = s;
    }
    __syncthreads();

    // load x for batch b = t
    const int b = t;
    const float* xp = cw_q + (size_t)b * (Dc * Ec) + (size_t)d * Ec;
    float xf[16];
    {
        float4 v0 = ((const float4*)xp)[0];
        float4 v1 = ((const float4*)xp)[1];
        float4 v2 = ((const float4*)xp)[2];
        float4 v3 = ((const float4*)xp)[3];
        xf[0]=v0.x; xf[1]=v0.y; xf[2]=v0.z; xf[3]=v0.w;
        xf[4]=v1.x; xf[5]=v1.y; xf[6]=v1.z; xf[7]=v1.w;
        xf[8]=v2.x; xf[9]=v2.y; xf[10]=v2.z; xf[11]=v2.w;
        xf[12]=v3.x; xf[13]=v3.y; xf[14]=v3.z; xf[15]=v3.w;
    }
    float x2 = 0.f;
    unsigned long long xx[16];
    #pragma unroll
    for (int e = 0; e < 16; e++) { x2 += xf[e] * xf[e]; xx[e] = pk2(xf[e], xf[e]); }

    const unsigned long long X2 = pk2(x2, x2);
    const unsigned long long NT = pk2(-2.0f, -2.0f);
    const unsigned long long ZZ = pk2(0.0f, 0.0f);
    const unsigned long long* c2p = (const unsigned long long*)c2f;

    float best = 3.4e38f;
    int bidx = 0;

    const ulonglong2* cp2 = (const ulonglong2*)cpack;  // 8 ulonglong2 per k-pair row
    #pragma unroll 4
    for (int p = 0; p < KH / 2; p++) {
        const ulonglong2* row = cp2 + p * 8;
        unsigned long long a0 = ZZ, a1 = ZZ;
        #pragma unroll
        for (int j = 0; j < 8; j++) {
            ulonglong2 v = row[j];
            a0 = f2fma(xx[2 * j],     v.x, a0);
            a1 = f2fma(xx[2 * j + 1], v.y, a1);
        }
        unsigned long long dot2  = f2add(a0, a1);
        unsigned long long s2    = f2add(X2, c2p[p]);          // x2 + c2 (ref order)
        unsigned long long dist2 = f2add(s2, f2mul(NT, dot2)); // (x2+c2) + (-2*xc)
        float d0, d1;
        upk2(dist2, d0, d1);
        float cd = d0; int ck = 2 * p;
        if (d1 < d0) { cd = d1; ck = 2 * p + 1; }   // first-min semantics
        if (cd < best) { best = cd; bidx = ck; }
    }

    // pack (orderable dist, global k): min over keys == first-occurrence argmin
    unsigned long long key = ((unsigned long long)orderable(best) << 32)
                           | (unsigned long long)(sp * KH + bidx);
    g_key[((size_t)sp * Dc + d) * Bc + b] = key;
}

// =====================================================================
// Kernel B: all outputs. grid = Dc, block = 256.
// Dynamic smem: acc 64 KB + sidx 1 KB + scnt 4 KB = 70656 B.
// =====================================================================
#define B_SMEM (65536 + 1024 + 4096)

extern __shared__ unsigned char smemB[];

__global__ void __launch_bounds__(256)
vq_outputs(const float* __restrict__ cw_q,
           const float* __restrict__ codebook,
           const float* __restrict__ ema,
           float* __restrict__ out)
{
    float* acc = (float*)smemB;                       // [Kc][Ec]
    int* sidx  = (int*)(smemB + 65536);               // [Bc]
    int* scnt  = (int*)(smemB + 65536 + 1024);        // [Kc]

    const int d = blockIdx.x;
    const int t = threadIdx.x;
    const int b = t;

    // combine split keys -> argmin index
    unsigned long long key = g_key[((size_t)0 * Dc + d) * Bc + b];
    #pragma unroll
    for (int sp = 1; sp < KSPLIT; sp++) {
        unsigned long long k2 = g_key[((size_t)sp * Dc + d) * Bc + b];
        if (k2 < key) key = k2;
    }
    const int idx = (int)(key & 0xFFFFFFFFull);
    sidx[b] = idx;

    // zero accumulator + histogram
    {
        float4 z = make_float4(0.f, 0.f, 0.f, 0.f);
        float4* av = (float4*)acc;
        #pragma unroll
        for (int i = t; i < (Kc * Ec) / 4; i += 256) av[i] = z;
        #pragma unroll
        for (int i = t; i < Kc; i += 256) scnt[i] = 0;
    }
    __syncthreads();

    // histogram + scatter x
    atomicAdd(&scnt[idx], 1);

    const float* xp = cw_q + (size_t)b * (Dc * Ec) + (size_t)d * Ec;
    float xf[16];
    {
        float4 v0 = ((const float4*)xp)[0];
        float4 v1 = ((const float4*)xp)[1];
        float4 v2 = ((const float4*)xp)[2];
        float4 v3 = ((const float4*)xp)[3];
        xf[0]=v0.x; xf[1]=v0.y; xf[2]=v0.z; xf[3]=v0.w;
        xf[4]=v1.x; xf[5]=v1.y; xf[6]=v1.z; xf[7]=v1.w;
        xf[8]=v2.x; xf[9]=v2.y; xf[10]=v2.z; xf[11]=v2.w;
        xf[12]=v3.x; xf[13]=v3.y; xf[14]=v3.z; xf[15]=v3.w;
    }
    #pragma unroll
    for (int e = 0; e < 16; e++) atomicAdd(&acc[idx * Ec + e], xf[e]);

    // cw_embed[b, d*16..] = codebook[d][idx]  (gmem gather, L2-resident)
    {
        const float4* ce = (const float4*)(codebook + ((size_t)d * Kc + idx) * Ec);
        float* dst = out + OFF_EMB + (size_t)b * (Dc * Ec) + (size_t)d * Ec;
        #pragma unroll
        for (int q = 0; q < 4; q++) ((float4*)dst)[q] = __ldg(ce + q);
    }
    __syncthreads();   // acc/scnt complete

    const float* emad = ema + (size_t)d * Kc;

    // new_ema_counts
    #pragma unroll
    for (int k = t; k < Kc; k += 256)
        out[OFF_NEC + (size_t)d * Kc + k] = 0.999f * emad[k] + 0.001f * (float)scnt[k];

    // new_codebook
    {
        const float* cbd = codebook + (size_t)d * (Kc * Ec);
        #pragma unroll
        for (int i = t; i < Kc * Ec; i += 256) {
            int k = i >> 4;
            float nc = 0.999f * cbd[i] + 0.001f * (acc[i] / (emad[k] + 1e-6f));
            out[OFF_NCB + (size_t)d * (Kc * Ec) + i] = nc;
        }
    }

    // one_hot slab: out_oh[bb, d, t*4 .. t*4+3]; bb == loop index (warp-uniform),
    // lane t covers float4 chunk c4 = t  -> pure coalesced STG.128 stream.
    {
        const size_t oh_d = OFF_OH + (size_t)d * Kc;
        const int base = t * 4;
        for (int bb = 0; bb < Bc; bb++) {
            int idx2 = sidx[bb];             // warp-uniform broadcast
            float4 v;
            v.x = (idx2 == base + 0) ? 1.0f : 0.0f;
            v.y = (idx2 == base + 1) ? 1.0f : 0.0f;
            v.z = (idx2 == base + 2) ? 1.0f : 0.0f;
            v.w = (idx2 == base + 3) ? 1.0f : 0.0f;
            ((float4*)(out + oh_d + (size_t)bb * (Dc * Kc)))[t] = v;
        }
    }
}

extern "C" void kernel_launch(void* const* d_in, const int* in_sizes, int n_in,
                              void* d_out, int out_size)
{
    const float* cw_q     = (const float*)d_in[0];
    const float* codebook = (const float*)d_in[1];
    const float* ema      = (const float*)d_in[2];
    float* out            = (float*)d_out;

    cudaFuncSetAttribute(vq_outputs, cudaFuncAttributeMaxDynamicSharedMemorySize, B_SMEM);

    vq_argmin<<<dim3(Dc, KSPLIT), 256>>>(cw_q, codebook);
    vq_outputs<<<Dc, 256, B_SMEM>>>(cw_q, codebook, ema, out);
}